// round 15
// baseline (speedup 1.0000x reference)
#include <cuda_runtime.h>

#define TT 512
typedef unsigned long long ull;

// ---------- packed f32x2 helpers ----------
__device__ __forceinline__ ull pk2(float a, float b) {
    ull r; asm("mov.b64 %0, {%1,%2};" : "=l"(r) : "f"(a), "f"(b)); return r;
}
__device__ __forceinline__ float sum2(ull v) {
    float a, b; asm("mov.b64 {%0,%1}, %2;" : "=f"(a), "=f"(b) : "l"(v));
    return a + b;
}
__device__ __forceinline__ ull fma2(ull a, ull b, ull c) {
    ull d; asm("fma.rn.f32x2 %0, %1, %2, %3;" : "=l"(d) : "l"(a), "l"(b), "l"(c));
    return d;
}
__device__ __forceinline__ ull mul2(ull a, ull b) {
    ull d; asm("mul.rn.f32x2 %0, %1, %2;" : "=l"(d) : "l"(a), "l"(b));
    return d;
}
__device__ __forceinline__ ull add2(ull a, ull b) {
    ull d; asm("add.rn.f32x2 %0, %1, %2;" : "=l"(d) : "l"(a), "l"(b));
    return d;
}

// ---------- activations ----------
__device__ __forceinline__ float tanhap_(float x) {     // MUFU tanh (recurrence)
    float r; asm("tanh.approx.f32 %0, %1;" : "=f"(r) : "f"(x)); return r;
}
__device__ __forceinline__ float rcpf_(float x) {
    float r; asm("rcp.approx.f32 %0, %1;" : "=f"(r) : "f"(x)); return r;
}
__device__ __forceinline__ float ex2f_(float x) {
    float r; asm("ex2.approx.f32 %0, %1;" : "=f"(r) : "f"(x)); return r;
}
__device__ __forceinline__ float tanh_(float x) {       // accurate (epilogue)
    float e = ex2f_(2.8853900817779268f * x);
    return 1.0f - 2.0f * rcpf_(e + 1.0f);
}

// pairwise named barrier: A-warp wp <-> B-warp wp, 64 threads
#define PBAR(id) asm volatile("bar.sync %0, %1;" :: "r"(id), "r"(64) : "memory")

// ---- x-phase: input-half accumulation for 4 tasks (bias folded) ----
__device__ __forceinline__ void xacc4(
    const ull* __restrict__ wv, ull bi0, ull bi1,
    const float* inb, ull* __restrict__ A0, ull* __restrict__ A1)
{
#pragma unroll
    for (int e = 0; e < 4; ++e) {
        ulonglong2 q = ((const ulonglong2*)(inb + 16 * e))[0];
        A0[e] = fma2(wv[0],  q.x, bi0);
        A1[e] = fma2(wv[16], q.x, bi1);
        A0[e] = fma2(wv[1],  q.y, A0[e]);
        A1[e] = fma2(wv[17], q.y, A1[e]);
    }
#pragma unroll
    for (int j = 1; j < 4; ++j) {
#pragma unroll
        for (int e = 0; e < 4; ++e) {
            ulonglong2 q = ((const ulonglong2*)(inb + 16 * e))[j];
            A0[e] = fma2(wv[2 * j],          q.x, A0[e]);
            A1[e] = fma2(wv[16 + 2 * j],     q.x, A1[e]);
            A0[e] = fma2(wv[2 * j + 1],      q.y, A0[e]);
            A1[e] = fma2(wv[16 + 2 * j + 1], q.y, A1[e]);
        }
    }
}

// ---- h-phase: recurrent half + asymmetric tail ----
__device__ __forceinline__ void hfin4(
    const ull* __restrict__ wv,
    const float* recb, ull* __restrict__ A0, ull* __restrict__ A1,
    float* __restrict__ c, float* dstb,
    float am, float ab, bool lo, int lane)
{
    ull b0[4], b1[4];
#pragma unroll
    for (int e = 0; e < 4; ++e) {
        ulonglong2 q = ((const ulonglong2*)(recb + 16 * e))[0];
        b0[e] = mul2(wv[8],  q.x);
        b1[e] = mul2(wv[24], q.x);
        b0[e] = fma2(wv[9],  q.y, b0[e]);
        b1[e] = fma2(wv[25], q.y, b1[e]);
    }
#pragma unroll
    for (int j = 1; j < 4; ++j) {
#pragma unroll
        for (int e = 0; e < 4; ++e) {
            ulonglong2 q = ((const ulonglong2*)(recb + 16 * e))[j];
            b0[e] = fma2(wv[8 + 2 * j],      q.x, b0[e]);
            b1[e] = fma2(wv[24 + 2 * j],     q.x, b1[e]);
            b0[e] = fma2(wv[8 + 2 * j + 1],  q.y, b0[e]);
            b1[e] = fma2(wv[24 + 2 * j + 1], q.y, b1[e]);
        }
    }
#pragma unroll
    for (int e = 0; e < 4; ++e) {
        float s0 = sum2(add2(A0[e], b0[e]));
        float s1 = sum2(add2(A1[e], b1[e]));
        float act0 = fmaf(0.5f, tanhap_(s0), 0.5f);   // i (lo) / f (hi)
        float act1 = fmaf(am, tanhap_(s1), ab);       // g (lo) / o (hi)
        float ig  = act0 * act1;
        float igx = __shfl_xor_sync(0xffffffffu, ig, 16);
        c[e] = fmaf(act0, c[e], igx);                 // hi: f*c + i*g
        float h = act1 * tanhap_(c[e]);               // hi: o * tanh(c)
        if (!lo) dstb[16 * e + lane - 16] = h;
    }
}

// CTA: 512 threads = 16 warps; 32 elems; grid 128.
// 4 steps per barrier interval. h0 ring 8-deep: interval P (t0%8==0) A writes
// slots 0-3 (steps t0..t0+3), B reads slots 4-7 (steps t0-4..t0-1); interval Q
// swaps halves. ONE PBAR per 4 steps. x staged a full interval ahead.
__global__ void __launch_bounds__(512, 1) lstm_pair7(
    const float* __restrict__ x,
    const float* __restrict__ Wih0, const float* __restrict__ Whh0,
    const float* __restrict__ bih0, const float* __restrict__ bhh0,
    const float* __restrict__ Wih1, const float* __restrict__ Whh1,
    const float* __restrict__ bih1, const float* __restrict__ bhh1,
    const float* __restrict__ Wproj, const float* __restrict__ bproj,
    const float* __restrict__ gamma, const float* __restrict__ beta,
    float* __restrict__ out)
{
    __shared__ __align__(16) float h0r[8][32][16];     // ring, 16 KB
    __shared__ __align__(16) float h1b[2][32][16];     // B-local double buffer
    __shared__ __align__(16) float4 xs4[2][4][8][16];  // [half][step][A-warp][e*4+q]

    const int tid = threadIdx.x;
    const int w    = tid >> 5;
    const int lane = tid & 31;
    const bool isA = (w < 8);
    const bool lo  = (lane < 16);
    const int wp   = w & 7;
    const int ebase = wp * 4;
    const int elem0 = blockIdx.x * 32;
    const int bid = wp + 1;

    // ---- weights into registers, sigmoid rows pre-scaled by 0.5 ----
    ull wv[32];
    ull bi0, bi1;
    {
        const float* Wi = isA ? Wih0 : Wih1;
        const float* Wh = isA ? Whh0 : Whh1;
        const float* bi = isA ? bih0 : bih1;
        const float* bh = isA ? bhh0 : bhh1;
        int rA = lane, rB = lane + 32;
        const float sA = 0.5f;
        const float sB = lo ? 1.0f : 0.5f;
#pragma unroll
        for (int kk = 0; kk < 8; ++kk) {
            wv[kk]      = pk2(sA * Wi[rA * 16 + 2 * kk], sA * Wi[rA * 16 + 2 * kk + 1]);
            wv[8 + kk]  = pk2(sA * Wh[rA * 16 + 2 * kk], sA * Wh[rA * 16 + 2 * kk + 1]);
            wv[16 + kk] = pk2(sB * Wi[rB * 16 + 2 * kk], sB * Wi[rB * 16 + 2 * kk + 1]);
            wv[24 + kk] = pk2(sB * Wh[rB * 16 + 2 * kk], sB * Wh[rB * 16 + 2 * kk + 1]);
        }
        bi0 = pk2(sA * (bi[rA] + bh[rA]), 0.f);
        bi1 = pk2(sB * (bi[rB] + bh[rB]), 0.f);
    }
    const float am = lo ? 1.0f : 0.5f;
    const float ab = lo ? 0.0f : 0.5f;

    for (int idx = tid; idx < 8 * 32 * 16; idx += 512) ((float*)h0r)[idx] = 0.f;
    for (int idx = tid; idx < 2 * 32 * 16; idx += 512) ((float*)h1b)[idx] = 0.f;

    // ---- warp-private x staging (A warps, lanes 0-15): rolling 2-reg prefetch ----
    const float4* xq = (const float4*)x;
    float4 xn0, xn1;
    if (isA && lo) {
        int e = lane >> 2, q = lane & 3;
        xq = (const float4*)(x + ((size_t)(elem0 + ebase + e) * TT) * 16) + q;
#pragma unroll
        for (int s = 0; s < 4; ++s) xs4[0][s][wp][lane] = xq[(size_t)s * 4]; // x[0..3]
        xn0 = xq[16];   // x[4]
        xn1 = xq[20];   // x[5]
    }

    float c[4] = {0.f, 0.f, 0.f, 0.f};

    const float* xr[2][4];
#pragma unroll
    for (int hh = 0; hh < 2; ++hh)
#pragma unroll
        for (int s = 0; s < 4; ++s) xr[hh][s] = (const float*)&xs4[hh][s][wp][0];
    float* h0p[8];
#pragma unroll
    for (int s = 0; s < 8; ++s) h0p[s] = &h0r[s][ebase][0];
    float* h1b0 = &h1b[0][ebase][0];
    float* h1b1 = &h1b[1][ebase][0];

    __syncthreads();

#pragma unroll 1
    for (int t0 = 0; t0 < TT; t0 += 8) {
        // ===== interval P: A steps t0..t0+3 -> slots 0-3; B steps t0-4..t0-1 <- slots 4-7 =====
        if (isA) {
            ull A0[4], A1[4];
            xacc4(wv, bi0, bi1, xr[0][0], A0, A1);
            hfin4(wv, h0p[7], A0, A1, c, h0p[0], am, ab, lo, lane);
            xacc4(wv, bi0, bi1, xr[0][1], A0, A1);
            __syncwarp();
            hfin4(wv, h0p[0], A0, A1, c, h0p[1], am, ab, lo, lane);
            if (lo) {                                   // stage x[t0+4], x[t0+5]
                xs4[1][0][wp][lane] = xn0;
                xs4[1][1][wp][lane] = xn1;
                xn0 = xq[(size_t)(t0 + 6) * 4];         // x[t0+6]  (<= 511)
                xn1 = xq[(size_t)(t0 + 7) * 4];         // x[t0+7]  (<= 511)
            }
            xacc4(wv, bi0, bi1, xr[0][2], A0, A1);
            __syncwarp();
            hfin4(wv, h0p[1], A0, A1, c, h0p[2], am, ab, lo, lane);
            xacc4(wv, bi0, bi1, xr[0][3], A0, A1);
            __syncwarp();
            hfin4(wv, h0p[2], A0, A1, c, h0p[3], am, ab, lo, lane);
            if (lo) {                                   // stage x[t0+6], x[t0+7]
                xs4[1][2][wp][lane] = xn0;
                xs4[1][3][wp][lane] = xn1;
                int i0 = t0 + 8  < TT ? t0 + 8  : TT - 1;
                int i1 = t0 + 9  < TT ? t0 + 9  : TT - 1;
                xn0 = xq[(size_t)i0 * 4];
                xn1 = xq[(size_t)i1 * 4];
            }
        } else if (t0 > 0) {
            ull A0[4], A1[4];
            xacc4(wv, bi0, bi1, h0p[4], A0, A1);
            hfin4(wv, h1b0, A0, A1, c, h1b1, am, ab, lo, lane);
            xacc4(wv, bi0, bi1, h0p[5], A0, A1);
            __syncwarp();
            hfin4(wv, h1b1, A0, A1, c, h1b0, am, ab, lo, lane);
            xacc4(wv, bi0, bi1, h0p[6], A0, A1);
            __syncwarp();
            hfin4(wv, h1b0, A0, A1, c, h1b1, am, ab, lo, lane);
            xacc4(wv, bi0, bi1, h0p[7], A0, A1);
            __syncwarp();
            hfin4(wv, h1b1, A0, A1, c, h1b0, am, ab, lo, lane);
        }
        PBAR(bid);
        // ===== interval Q: A steps t0+4..t0+7 -> slots 4-7; B steps t0..t0+3 <- slots 0-3 =====
        if (isA) {
            ull A0[4], A1[4];
            xacc4(wv, bi0, bi1, xr[1][0], A0, A1);
            hfin4(wv, h0p[3], A0, A1, c, h0p[4], am, ab, lo, lane);
            xacc4(wv, bi0, bi1, xr[1][1], A0, A1);
            __syncwarp();
            hfin4(wv, h0p[4], A0, A1, c, h0p[5], am, ab, lo, lane);
            if (lo) {                                   // stage x[t0+8], x[t0+9]
                xs4[0][0][wp][lane] = xn0;
                xs4[0][1][wp][lane] = xn1;
                int i0 = t0 + 10 < TT ? t0 + 10 : TT - 1;
                int i1 = t0 + 11 < TT ? t0 + 11 : TT - 1;
                xn0 = xq[(size_t)i0 * 4];
                xn1 = xq[(size_t)i1 * 4];
            }
            xacc4(wv, bi0, bi1, xr[1][2], A0, A1);
            __syncwarp();
            hfin4(wv, h0p[5], A0, A1, c, h0p[6], am, ab, lo, lane);
            xacc4(wv, bi0, bi1, xr[1][3], A0, A1);
            __syncwarp();
            hfin4(wv, h0p[6], A0, A1, c, h0p[7], am, ab, lo, lane);
            if (lo) {                                   // stage x[t0+10], x[t0+11]
                xs4[0][2][wp][lane] = xn0;
                xs4[0][3][wp][lane] = xn1;
                int i0 = t0 + 12 < TT ? t0 + 12 : TT - 1;
                int i1 = t0 + 13 < TT ? t0 + 13 : TT - 1;
                xn0 = xq[(size_t)i0 * 4];
                xn1 = xq[(size_t)i1 * 4];
            }
        } else {
            ull A0[4], A1[4];
            xacc4(wv, bi0, bi1, h0p[0], A0, A1);
            hfin4(wv, h1b0, A0, A1, c, h1b1, am, ab, lo, lane);
            xacc4(wv, bi0, bi1, h0p[1], A0, A1);
            __syncwarp();
            hfin4(wv, h1b1, A0, A1, c, h1b0, am, ab, lo, lane);
            xacc4(wv, bi0, bi1, h0p[2], A0, A1);
            __syncwarp();
            hfin4(wv, h1b0, A0, A1, c, h1b1, am, ab, lo, lane);
            xacc4(wv, bi0, bi1, h0p[3], A0, A1);
            __syncwarp();
            hfin4(wv, h1b1, A0, A1, c, h1b0, am, ab, lo, lane);
        }
        PBAR(bid);
    }

    // ---- tail: B steps 508..511 <- slots 4-7 ----
    if (!isA) {
        ull A0[4], A1[4];
        xacc4(wv, bi0, bi1, h0p[4], A0, A1);
        hfin4(wv, h1b0, A0, A1, c, h1b1, am, ab, lo, lane);
        xacc4(wv, bi0, bi1, h0p[5], A0, A1);
        __syncwarp();
        hfin4(wv, h1b1, A0, A1, c, h1b0, am, ab, lo, lane);
        xacc4(wv, bi0, bi1, h0p[6], A0, A1);
        __syncwarp();
        hfin4(wv, h1b0, A0, A1, c, h1b1, am, ab, lo, lane);
        xacc4(wv, bi0, bi1, h0p[7], A0, A1);
        __syncwarp();
        hfin4(wv, h1b1, A0, A1, c, h1b0, am, ab, lo, lane);
    }
    __syncthreads();

    // ---- projection + LayerNorm + tanh (warp 0; final h1 in h1b[0]) ----
    if (w == 0) {
        float hv[16];
#pragma unroll
        for (int k = 0; k < 16; ++k) hv[k] = h1b[0][lane][k];
        float z[16];
        float mu = 0.f;
#pragma unroll
        for (int j = 0; j < 16; ++j) {
            float s = bproj[j];
#pragma unroll
            for (int k = 0; k < 16; ++k) s = fmaf(Wproj[j * 16 + k], hv[k], s);
            z[j] = s;
            mu += s;
        }
        mu *= (1.0f / 16.0f);
        float var = 0.f;
#pragma unroll
        for (int j = 0; j < 16; ++j) { float d = z[j] - mu; var = fmaf(d, d, var); }
        var *= (1.0f / 16.0f);
        float rs = rsqrtf(var + 1e-5f);
#pragma unroll
        for (int j = 0; j < 16; ++j) {
            float zn = (z[j] - mu) * rs * gamma[j] + beta[j];
            out[(size_t)(elem0 + lane) * 16 + j] = tanh_(zn);
        }
    }
}

extern "C" void kernel_launch(void* const* d_in, const int* in_sizes, int n_in,
                              void* d_out, int out_size) {
    const float* x     = (const float*)d_in[0];
    const float* Wih0  = (const float*)d_in[1];
    const float* Whh0  = (const float*)d_in[2];
    const float* bih0  = (const float*)d_in[3];
    const float* bhh0  = (const float*)d_in[4];
    const float* Wih1  = (const float*)d_in[5];
    const float* Whh1  = (const float*)d_in[6];
    const float* bih1  = (const float*)d_in[7];
    const float* bhh1  = (const float*)d_in[8];
    const float* Wproj = (const float*)d_in[9];
    const float* bproj = (const float*)d_in[10];
    const float* gamma = (const float*)d_in[11];
    const float* beta  = (const float*)d_in[12];
    float* out = (float*)d_out;

    int B = in_sizes[0] / (TT * 16);   // 4096
    int grid = B / 32;                 // 128 CTAs

    lstm_pair7<<<grid, 512>>>(x, Wih0, Whh0, bih0, bhh0,
                              Wih1, Whh1, bih1, bhh1,
                              Wproj, bproj, gamma, beta, out);
}

// round 16
// speedup vs baseline: 1.0269x; 1.0269x over previous
#include <cuda_runtime.h>

#define TT 512
typedef unsigned long long ull;

// ---------- packed f32x2 helpers ----------
__device__ __forceinline__ ull pk2(float a, float b) {
    ull r; asm("mov.b64 %0, {%1,%2};" : "=l"(r) : "f"(a), "f"(b)); return r;
}
__device__ __forceinline__ float sum2(ull v) {
    float a, b; asm("mov.b64 {%0,%1}, %2;" : "=f"(a), "=f"(b) : "l"(v));
    return a + b;
}
__device__ __forceinline__ ull fma2(ull a, ull b, ull c) {
    ull d; asm("fma.rn.f32x2 %0, %1, %2, %3;" : "=l"(d) : "l"(a), "l"(b), "l"(c));
    return d;
}
__device__ __forceinline__ ull mul2(ull a, ull b) {
    ull d; asm("mul.rn.f32x2 %0, %1, %2;" : "=l"(d) : "l"(a), "l"(b));
    return d;
}
__device__ __forceinline__ ull add2(ull a, ull b) {
    ull d; asm("add.rn.f32x2 %0, %1, %2;" : "=l"(d) : "l"(a), "l"(b));
    return d;
}

// ---------- activations ----------
__device__ __forceinline__ float tanhap_(float x) {     // MUFU tanh (recurrence)
    float r; asm("tanh.approx.f32 %0, %1;" : "=f"(r) : "f"(x)); return r;
}
__device__ __forceinline__ float rcpf_(float x) {
    float r; asm("rcp.approx.f32 %0, %1;" : "=f"(r) : "f"(x)); return r;
}
__device__ __forceinline__ float ex2f_(float x) {
    float r; asm("ex2.approx.f32 %0, %1;" : "=f"(r) : "f"(x)); return r;
}
__device__ __forceinline__ float tanh_(float x) {       // accurate (epilogue)
    float e = ex2f_(2.8853900817779268f * x);
    return 1.0f - 2.0f * rcpf_(e + 1.0f);
}

// pairwise named barrier: A-warp wp <-> B-warp wp, 64 threads
#define PBAR(id) asm volatile("bar.sync %0, %1;" :: "r"(id), "r"(64) : "memory")

// ---- x-phase: input-half accumulation for 4 tasks (bias folded) ----
__device__ __forceinline__ void xacc4(
    const ull* __restrict__ wv, ull bi0, ull bi1,
    const float* inb, ull* __restrict__ A0, ull* __restrict__ A1)
{
#pragma unroll
    for (int e = 0; e < 4; ++e) {
        ulonglong2 q = ((const ulonglong2*)(inb + 16 * e))[0];
        A0[e] = fma2(wv[0],  q.x, bi0);
        A1[e] = fma2(wv[16], q.x, bi1);
        A0[e] = fma2(wv[1],  q.y, A0[e]);
        A1[e] = fma2(wv[17], q.y, A1[e]);
    }
#pragma unroll
    for (int j = 1; j < 4; ++j) {
#pragma unroll
        for (int e = 0; e < 4; ++e) {
            ulonglong2 q = ((const ulonglong2*)(inb + 16 * e))[j];
            A0[e] = fma2(wv[2 * j],          q.x, A0[e]);
            A1[e] = fma2(wv[16 + 2 * j],     q.x, A1[e]);
            A0[e] = fma2(wv[2 * j + 1],      q.y, A0[e]);
            A1[e] = fma2(wv[16 + 2 * j + 1], q.y, A1[e]);
        }
    }
}

// ---- h-phase: recurrent half + asymmetric tail ----
__device__ __forceinline__ void hfin4(
    const ull* __restrict__ wv,
    const float* recb, ull* __restrict__ A0, ull* __restrict__ A1,
    float* __restrict__ c, float* dstb,
    float am, float ab, bool lo, int lane)
{
    ull b0[4], b1[4];
#pragma unroll
    for (int e = 0; e < 4; ++e) {
        ulonglong2 q = ((const ulonglong2*)(recb + 16 * e))[0];
        b0[e] = mul2(wv[8],  q.x);
        b1[e] = mul2(wv[24], q.x);
        b0[e] = fma2(wv[9],  q.y, b0[e]);
        b1[e] = fma2(wv[25], q.y, b1[e]);
    }
#pragma unroll
    for (int j = 1; j < 4; ++j) {
#pragma unroll
        for (int e = 0; e < 4; ++e) {
            ulonglong2 q = ((const ulonglong2*)(recb + 16 * e))[j];
            b0[e] = fma2(wv[8 + 2 * j],      q.x, b0[e]);
            b1[e] = fma2(wv[24 + 2 * j],     q.x, b1[e]);
            b0[e] = fma2(wv[8 + 2 * j + 1],  q.y, b0[e]);
            b1[e] = fma2(wv[24 + 2 * j + 1], q.y, b1[e]);
        }
    }
#pragma unroll
    for (int e = 0; e < 4; ++e) {
        float s0 = sum2(add2(A0[e], b0[e]));
        float s1 = sum2(add2(A1[e], b1[e]));
        float act0 = fmaf(0.5f, tanhap_(s0), 0.5f);   // i (lo) / f (hi)
        float act1 = fmaf(am, tanhap_(s1), ab);       // g (lo) / o (hi)
        float ig  = act0 * act1;
        float igx = __shfl_xor_sync(0xffffffffu, ig, 16);
        c[e] = fmaf(act0, c[e], igx);                 // hi: f*c + i*g
        float h = act1 * tanhap_(c[e]);               // hi: o * tanh(c)
        if (!lo) dstb[16 * e + lane - 16] = h;
    }
}

// CTA: 512 threads = 16 warps; 32 elems; grid 128.  (R14 structure.)
// 2 steps per barrier interval; h0 ring 4-deep; h1 B-local double buffer.
// NEW: A-warps compute the NEXT interval's first x-phase above the PBAR
// (x staging is warp-private, ordered by __syncwarp) -> every A step enters
// its h-phase with the x-half already accumulated.
__global__ void __launch_bounds__(512, 1) lstm_pair8(
    const float* __restrict__ x,
    const float* __restrict__ Wih0, const float* __restrict__ Whh0,
    const float* __restrict__ bih0, const float* __restrict__ bhh0,
    const float* __restrict__ Wih1, const float* __restrict__ Whh1,
    const float* __restrict__ bih1, const float* __restrict__ bhh1,
    const float* __restrict__ Wproj, const float* __restrict__ bproj,
    const float* __restrict__ gamma, const float* __restrict__ beta,
    float* __restrict__ out)
{
    __shared__ __align__(16) float h0r[4][32][16];   // ring, 8 KB
    __shared__ __align__(16) float h1b[2][32][16];   // B-local double buffer
    __shared__ __align__(16) float4 xs4[4][8][16];   // [slot][A-warp][e*4+q]

    const int tid = threadIdx.x;
    const int w    = tid >> 5;
    const int lane = tid & 31;
    const bool isA = (w < 8);
    const bool lo  = (lane < 16);
    const int wp   = w & 7;
    const int ebase = wp * 4;
    const int elem0 = blockIdx.x * 32;
    const int bid = wp + 1;

    // ---- weights into registers, sigmoid rows pre-scaled by 0.5 ----
    ull wv[32];
    ull bi0, bi1;
    {
        const float* Wi = isA ? Wih0 : Wih1;
        const float* Wh = isA ? Whh0 : Whh1;
        const float* bi = isA ? bih0 : bih1;
        const float* bh = isA ? bhh0 : bhh1;
        int rA = lane, rB = lane + 32;
        const float sA = 0.5f;
        const float sB = lo ? 1.0f : 0.5f;
#pragma unroll
        for (int kk = 0; kk < 8; ++kk) {
            wv[kk]      = pk2(sA * Wi[rA * 16 + 2 * kk], sA * Wi[rA * 16 + 2 * kk + 1]);
            wv[8 + kk]  = pk2(sA * Wh[rA * 16 + 2 * kk], sA * Wh[rA * 16 + 2 * kk + 1]);
            wv[16 + kk] = pk2(sB * Wi[rB * 16 + 2 * kk], sB * Wi[rB * 16 + 2 * kk + 1]);
            wv[24 + kk] = pk2(sB * Wh[rB * 16 + 2 * kk], sB * Wh[rB * 16 + 2 * kk + 1]);
        }
        bi0 = pk2(sA * (bi[rA] + bh[rA]), 0.f);
        bi1 = pk2(sB * (bi[rB] + bh[rB]), 0.f);
    }
    const float am = lo ? 1.0f : 0.5f;
    const float ab = lo ? 0.0f : 0.5f;

    for (int idx = tid; idx < 4 * 32 * 16; idx += 512) ((float*)h0r)[idx] = 0.f;
    for (int idx = tid; idx < 2 * 32 * 16; idx += 512) ((float*)h1b)[idx] = 0.f;

    // ---- warp-private x staging (A warps, lanes 0-15) ----
    const float4* xq = (const float4*)x;
    float4 xn0, xn1;
    if (isA && lo) {
        int e = lane >> 2, q = lane & 3;
        xq = (const float4*)(x + ((size_t)(elem0 + ebase + e) * TT) * 16) + q;
        xs4[0][wp][lane] = xq[0];    // x[0]
        xs4[1][wp][lane] = xq[4];    // x[1]
        xn0 = xq[8];                 // x[2]
        xn1 = xq[12];                // x[3]
    }

    float c[4] = {0.f, 0.f, 0.f, 0.f};
    ull A0[4], A1[4], B0[4], B1[4];

    const float* xr0 = (const float*)&xs4[0][wp][0];
    const float* xr1 = (const float*)&xs4[1][wp][0];
    const float* xr2 = (const float*)&xs4[2][wp][0];
    const float* xr3 = (const float*)&xs4[3][wp][0];
    float* h0s0 = &h0r[0][ebase][0];
    float* h0s1 = &h0r[1][ebase][0];
    float* h0s2 = &h0r[2][ebase][0];
    float* h0s3 = &h0r[3][ebase][0];
    float* h1b0 = &h1b[0][ebase][0];
    float* h1b1 = &h1b[1][ebase][0];

    __syncthreads();

    // preamble: A's x-phase for step 0 (xs[0] staged before __syncthreads)
    if (isA) xacc4(wv, bi0, bi1, xr0, A0, A1);

#pragma unroll 1
    for (int t0 = 0; t0 < TT; t0 += 4) {
        // ===== interval P: A steps t0,t0+1 (slots 0,1); B steps t0-2,t0-1 =====
        if (isA) {
            // A0/A1 hold x-phase of step t0 (computed before the PBAR)
            hfin4(wv, h0s3, A0, A1, c, h0s0, am, ab, lo, lane);
            xacc4(wv, bi0, bi1, xr1, B0, B1);        // x-phase step t0+1
            __syncwarp();
            hfin4(wv, h0s0, B0, B1, c, h0s1, am, ab, lo, lane);
            if (lo) {                                // stage next interval (Q)
                xs4[2][wp][lane] = xn0;              // x[t0+2]
                xs4[3][wp][lane] = xn1;              // x[t0+3]
                int tf0 = t0 + 4 < TT ? t0 + 4 : TT - 1;
                int tf1 = t0 + 5 < TT ? t0 + 5 : TT - 1;
                xn0 = xq[(size_t)tf0 * 4];
                xn1 = xq[(size_t)tf1 * 4];
            }
            __syncwarp();                            // staged x visible warp-wide
            xacc4(wv, bi0, bi1, xr2, A0, A1);        // x-phase step t0+2 (above PBAR)
        } else if (t0 > 0) {
            xacc4(wv, bi0, bi1, h0s2, A0, A1);       // input h0[t0-2]
            hfin4(wv, h1b0, A0, A1, c, h1b1, am, ab, lo, lane);
            xacc4(wv, bi0, bi1, h0s3, B0, B1);       // h0[t0-1] ready
            __syncwarp();
            hfin4(wv, h1b1, B0, B1, c, h1b0, am, ab, lo, lane);
        }
        PBAR(bid);
        // ===== interval Q: A steps t0+2,t0+3 (slots 2,3); B steps t0,t0+1 =====
        if (isA) {
            hfin4(wv, h0s1, A0, A1, c, h0s2, am, ab, lo, lane);
            xacc4(wv, bi0, bi1, xr3, B0, B1);
            __syncwarp();
            hfin4(wv, h0s2, B0, B1, c, h0s3, am, ab, lo, lane);
            if (lo) {                                // stage next interval (P)
                xs4[0][wp][lane] = xn0;              // x[t0+4]
                xs4[1][wp][lane] = xn1;              // x[t0+5]
                int tf0 = t0 + 6 < TT ? t0 + 6 : TT - 1;
                int tf1 = t0 + 7 < TT ? t0 + 7 : TT - 1;
                xn0 = xq[(size_t)tf0 * 4];
                xn1 = xq[(size_t)tf1 * 4];
            }
            __syncwarp();
            xacc4(wv, bi0, bi1, xr0, A0, A1);        // x-phase step t0+4 (above PBAR)
        } else {
            xacc4(wv, bi0, bi1, h0s0, A0, A1);       // input h0[t0]
            hfin4(wv, h1b0, A0, A1, c, h1b1, am, ab, lo, lane);
            xacc4(wv, bi0, bi1, h0s1, B0, B1);
            __syncwarp();
            hfin4(wv, h1b1, B0, B1, c, h1b0, am, ab, lo, lane);
        }
        PBAR(bid);
    }

    // ---- tail: B steps 510 (slot 2), 511 (slot 3) ----
    if (!isA) {
        xacc4(wv, bi0, bi1, h0s2, A0, A1);
        hfin4(wv, h1b0, A0, A1, c, h1b1, am, ab, lo, lane);
        xacc4(wv, bi0, bi1, h0s3, B0, B1);
        __syncwarp();
        hfin4(wv, h1b1, B0, B1, c, h1b0, am, ab, lo, lane);
    }
    __syncthreads();

    // ---- projection + LayerNorm + tanh (warp 0; final h1 in h1b[0]) ----
    if (w == 0) {
        float hv[16];
#pragma unroll
        for (int k = 0; k < 16; ++k) hv[k] = h1b[0][lane][k];
        float z[16];
        float mu = 0.f;
#pragma unroll
        for (int j = 0; j < 16; ++j) {
            float s = bproj[j];
#pragma unroll
            for (int k = 0; k < 16; ++k) s = fmaf(Wproj[j * 16 + k], hv[k], s);
            z[j] = s;
            mu += s;
        }
        mu *= (1.0f / 16.0f);
        float var = 0.f;
#pragma unroll
        for (int j = 0; j < 16; ++j) { float d = z[j] - mu; var = fmaf(d, d, var); }
        var *= (1.0f / 16.0f);
        float rs = rsqrtf(var + 1e-5f);
#pragma unroll
        for (int j = 0; j < 16; ++j) {
            float zn = (z[j] - mu) * rs * gamma[j] + beta[j];
            out[(size_t)(elem0 + lane) * 16 + j] = tanh_(zn);
        }
    }
}

extern "C" void kernel_launch(void* const* d_in, const int* in_sizes, int n_in,
                              void* d_out, int out_size) {
    const float* x     = (const float*)d_in[0];
    const float* Wih0  = (const float*)d_in[1];
    const float* Whh0  = (const float*)d_in[2];
    const float* bih0  = (const float*)d_in[3];
    const float* bhh0  = (const float*)d_in[4];
    const float* Wih1  = (const float*)d_in[5];
    const float* Whh1  = (const float*)d_in[6];
    const float* bih1  = (const float*)d_in[7];
    const float* bhh1  = (const float*)d_in[8];
    const float* Wproj = (const float*)d_in[9];
    const float* bproj = (const float*)d_in[10];
    const float* gamma = (const float*)d_in[11];
    const float* beta  = (const float*)d_in[12];
    float* out = (float*)d_out;

    int B = in_sizes[0] / (TT * 16);   // 4096
    int grid = B / 32;                 // 128 CTAs

    lstm_pair8<<<grid, 512>>>(x, Wih0, Whh0, bih0, bhh0,
                              Wih1, Whh1, bih1, bhh1,
                              Wproj, bproj, gamma, beta, out);
}